// round 4
// baseline (speedup 1.0000x reference)
#include <cuda_runtime.h>
#include <math.h>
#include <stdint.h>
#include <mma.h>

using namespace nvcuda;

#define ND 100000
#define NP 100000
#define EE 800000

// ---------------- scratch (__device__ globals; no allocations) ----------------
__device__ float g_hd[ND * 128];
__device__ float g_hp[NP * 128];
__device__ float g_fs_dp[ND * 128];
__device__ float g_fd_dp[NP * 128];
__device__ float g_fs_pd[NP * 128];
__device__ float g_fd_pd[ND * 128];
__device__ float g_agg_p[NP * 128];
__device__ float g_agg_d[ND * 128];
__device__ float g_el_dp[ND * 4];
__device__ float g_er_dp[NP * 4];
__device__ float g_el_pd[NP * 4];
__device__ float g_er_pd[ND * 4];
__device__ float g_s_p[NP * 4];
__device__ float g_s_d[ND * 4];
__device__ float g_ex_dp[EE * 4];
__device__ float g_ex_pd[EE * 4];

// ---------------- helpers ----------------
__device__ __forceinline__ float cvt_tf32(float a) {
    uint32_t r;
    asm("cvt.rna.tf32.f32 %0, %1;" : "=r"(r) : "f"(a));
    return __uint_as_float(r);
}
__device__ __forceinline__ void red_add_v4(float* addr, float4 v) {
    asm volatile("red.global.add.v4.f32 [%0], {%1,%2,%3,%4};"
                 :: "l"(addr), "f"(v.x), "f"(v.y), "f"(v.z), "f"(v.w) : "memory");
}
__device__ __forceinline__ float lrelu_exp(float v) {
    // leaky_relu(v,0.2) then exp; softmax max-shift omitted (shift-invariant, |e| = O(1))
    return expf(v > 0.f ? v : 0.2f * v);
}

// ---------------- tf32 wmma GEMM: C[n,128] = A[n,128] @ B[128,128] (+bias,+relu) ----------------
// 3-term tf32 split for fp32-class accuracy: D += Ahi*Bhi + Ahi*Blo + Alo*Bhi.
// CTA tile 128x128, K streamed in two 64-chunks, 8 warps each own a 32x64 tile.
#define A_LD 72     // 64 + 8 pad (floats)
#define B_LD 136    // 128 + 8 pad (floats)
#define SM_AH 0
#define SM_AL (128 * A_LD)
#define SM_BH (2 * 128 * A_LD)
#define SM_BL (2 * 128 * A_LD + 64 * B_LD)
#define GW_SMEM ((2 * 128 * A_LD + 2 * 64 * B_LD) * 4)   // 143360 bytes

__global__ void __launch_bounds__(256, 1)
gemm_wmma(const float* __restrict__ A, const float* __restrict__ B,
          const float* __restrict__ bias, float* __restrict__ C,
          int n, int relu_flag)
{
    extern __shared__ float sm[];
    const int tid = threadIdx.x;
    const int warp = tid >> 5;
    const int rowbase = blockIdx.x * 128;
    const int wm = warp & 3;          // row group: rows wm*32 .. +31
    const int wn = warp >> 2;         // col group: cols wn*64 .. +63

    wmma::fragment<wmma::accumulator, 16, 16, 8, float> acc[2][4];
    #pragma unroll
    for (int i = 0; i < 2; i++)
        #pragma unroll
        for (int j = 0; j < 4; j++) wmma::fill_fragment(acc[i][j], 0.f);

    #pragma unroll
    for (int c = 0; c < 2; c++) {
        if (c) __syncthreads();   // smem reuse barrier
        // A chunk: 128 rows x 64 cols -> As_hi/As_lo (split at store)
        #pragma unroll
        for (int t = tid; t < 2048; t += 256) {
            int r = t >> 4, c4 = t & 15;
            int gr = rowbase + r;
            float4 v = make_float4(0.f, 0.f, 0.f, 0.f);
            if (gr < n) v = *(const float4*)(A + (size_t)gr * 128 + c * 64 + c4 * 4);
            float4 h, l;
            h.x = cvt_tf32(v.x); l.x = cvt_tf32(v.x - h.x);
            h.y = cvt_tf32(v.y); l.y = cvt_tf32(v.y - h.y);
            h.z = cvt_tf32(v.z); l.z = cvt_tf32(v.z - h.z);
            h.w = cvt_tf32(v.w); l.w = cvt_tf32(v.w - h.w);
            *(float4*)(sm + SM_AH + r * A_LD + c4 * 4) = h;
            *(float4*)(sm + SM_AL + r * A_LD + c4 * 4) = l;
        }
        // B chunk: 64 rows (k) x 128 cols (n) — W is [k][n] row-major, no transpose
        #pragma unroll
        for (int t = tid; t < 2048; t += 256) {
            int r = t >> 5, c4 = t & 31;
            float4 v = *(const float4*)(B + (size_t)(c * 64 + r) * 128 + c4 * 4);
            float4 h, l;
            h.x = cvt_tf32(v.x); l.x = cvt_tf32(v.x - h.x);
            h.y = cvt_tf32(v.y); l.y = cvt_tf32(v.y - h.y);
            h.z = cvt_tf32(v.z); l.z = cvt_tf32(v.z - h.z);
            h.w = cvt_tf32(v.w); l.w = cvt_tf32(v.w - h.w);
            *(float4*)(sm + SM_BH + r * B_LD + c4 * 4) = h;
            *(float4*)(sm + SM_BL + r * B_LD + c4 * 4) = l;
        }
        __syncthreads();

        #pragma unroll
        for (int ks = 0; ks < 8; ks++) {
            wmma::fragment<wmma::matrix_a, 16, 16, 8, wmma::precision::tf32, wmma::row_major> ah[2], al[2];
            wmma::fragment<wmma::matrix_b, 16, 16, 8, wmma::precision::tf32, wmma::row_major> bh[4], bl[4];
            #pragma unroll
            for (int i = 0; i < 2; i++) {
                const float* pa = sm + (wm * 32 + i * 16) * A_LD + ks * 8;
                wmma::load_matrix_sync(ah[i], pa + SM_AH, A_LD);
                wmma::load_matrix_sync(al[i], pa + SM_AL, A_LD);
            }
            #pragma unroll
            for (int j = 0; j < 4; j++) {
                const float* pb = sm + ks * 8 * B_LD + wn * 64 + j * 16;
                wmma::load_matrix_sync(bh[j], pb + SM_BH, B_LD);
                wmma::load_matrix_sync(bl[j], pb + SM_BL, B_LD);
            }
            #pragma unroll
            for (int i = 0; i < 2; i++)
                #pragma unroll
                for (int j = 0; j < 4; j++) {
                    wmma::mma_sync(acc[i][j], ah[i], bh[j], acc[i][j]);
                    wmma::mma_sync(acc[i][j], ah[i], bl[j], acc[i][j]);
                    wmma::mma_sync(acc[i][j], al[i], bh[j], acc[i][j]);
                }
        }
    }

    // epilogue: acc -> smem [128][B_LD] -> coalesced global with bias/relu
    __syncthreads();
    #pragma unroll
    for (int i = 0; i < 2; i++)
        #pragma unroll
        for (int j = 0; j < 4; j++)
            wmma::store_matrix_sync(sm + (wm * 32 + i * 16) * B_LD + wn * 64 + j * 16,
                                    acc[i][j], B_LD, wmma::mem_row_major);
    __syncthreads();
    #pragma unroll
    for (int t = tid; t < 4096; t += 256) {
        int r = t >> 5, c4 = t & 31;
        int gr = rowbase + r;
        if (gr >= n) continue;
        float4 o = *(const float4*)(sm + r * B_LD + c4 * 4);
        if (bias) {
            o.x += __ldg(bias + c4 * 4 + 0);
            o.y += __ldg(bias + c4 * 4 + 1);
            o.z += __ldg(bias + c4 * 4 + 2);
            o.w += __ldg(bias + c4 * 4 + 3);
        }
        if (relu_flag) {
            o.x = fmaxf(o.x, 0.f); o.y = fmaxf(o.y, 0.f);
            o.z = fmaxf(o.z, 0.f); o.w = fmaxf(o.w, 0.f);
        }
        *(float4*)(C + (size_t)gr * 128 + c4 * 4) = o;
    }
}

// ---------------- per-head dot: out[n][h] = sum_d F[n][h*32+d] * attn[h][d] ----------------
__global__ void headdot(const float* __restrict__ F, const float* __restrict__ attn,
                        float* __restrict__ out, int n)
{
    int gw = (int)((blockIdx.x * (size_t)blockDim.x + threadIdx.x) >> 5);
    int lane = threadIdx.x & 31;
    if (gw >= n) return;
    int head = lane >> 3, part = lane & 7;
    float4 f = ((const float4*)F)[(size_t)gw * 32 + lane];
    float4 av = ((const float4*)attn)[head * 8 + part];
    float v = f.x * av.x + f.y * av.y + f.z * av.z + f.w * av.w;
    v += __shfl_down_sync(0xffffffffu, v, 4);
    v += __shfl_down_sync(0xffffffffu, v, 2);
    v += __shfl_down_sync(0xffffffffu, v, 1);
    if (part == 0) out[gw * 4 + head] = v;
}

__global__ void init_agg(float* __restrict__ agg, const float* __restrict__ bias,
                         float* __restrict__ ssum, int n)
{
    size_t i = blockIdx.x * (size_t)blockDim.x + threadIdx.x;
    if (i < (size_t)n * 128) agg[i] = bias[i & 127];
    if (i < (size_t)n * 4) ssum[i] = 0.f;
}

__global__ void edge_pass1(const int* __restrict__ src, const int* __restrict__ dst,
                           const float* __restrict__ el, const float* __restrict__ er,
                           float* __restrict__ exb, float* __restrict__ ssum, int ne)
{
    int e = blockIdx.x * blockDim.x + threadIdx.x;
    if (e >= ne) return;
    int s = src[e], d = dst[e];
    float4 a = ((const float4*)el)[s];
    float4 b = ((const float4*)er)[d];
    float4 x;
    x.x = lrelu_exp(a.x + b.x);
    x.y = lrelu_exp(a.y + b.y);
    x.z = lrelu_exp(a.z + b.z);
    x.w = lrelu_exp(a.w + b.w);
    ((float4*)exb)[e] = x;
    red_add_v4(ssum + (size_t)d * 4, x);
}

__global__ void edge_pass2(const int* __restrict__ src, const int* __restrict__ dst,
                           const float* __restrict__ exb, const float* __restrict__ ssum,
                           const float* __restrict__ fs, float* __restrict__ agg, int ne)
{
    int w = (int)((blockIdx.x * (size_t)blockDim.x + threadIdx.x) >> 5);
    int lane = threadIdx.x & 31;
    if (w >= ne) return;
    int s = src[w], d = dst[w];
    int head = lane >> 3;
    float a = exb[(size_t)w * 4 + head] / ssum[(size_t)d * 4 + head];
    float4 f = ((const float4*)fs)[(size_t)s * 32 + lane];
    float4 m = make_float4(a * f.x, a * f.y, a * f.z, a * f.w);
    red_add_v4(agg + (size_t)d * 128 + lane * 4, m);
}

// ---------------- launch ----------------
extern "C" void kernel_launch(void* const* d_in, const int* in_sizes, int n_in,
                              void* d_out, int out_size)
{
    const float* x_drug  = (const float*)d_in[0];
    const float* x_prot  = (const float*)d_in[1];
    const int*   src_dp  = (const int*)d_in[2];
    const int*   dst_dp  = (const int*)d_in[3];
    const int*   src_pd  = (const int*)d_in[4];
    const int*   dst_pd  = (const int*)d_in[5];
    const float* W_in_d  = (const float*)d_in[6];
    const float* b_in_d  = (const float*)d_in[7];
    const float* W_in_p  = (const float*)d_in[8];
    const float* b_in_p  = (const float*)d_in[9];
    const float* W_dp    = (const float*)d_in[10];
    const float* al_dp   = (const float*)d_in[11];
    const float* ar_dp   = (const float*)d_in[12];
    const float* bias_dp = (const float*)d_in[13];
    const float* W_pd    = (const float*)d_in[14];
    const float* al_pd   = (const float*)d_in[15];
    const float* ar_pd   = (const float*)d_in[16];
    const float* bias_pd = (const float*)d_in[17];
    const float* W_out_d = (const float*)d_in[18];
    const float* b_out_d = (const float*)d_in[19];
    const float* W_out_p = (const float*)d_in[20];
    const float* b_out_p = (const float*)d_in[21];
    float* out = (float*)d_out;

    float *hd, *hp, *fs_dp, *fd_dp, *fs_pd, *fd_pd, *agg_p, *agg_d;
    float *el_dp, *er_dp, *el_pd, *er_pd, *s_p, *s_d, *ex_dp, *ex_pd;
    cudaGetSymbolAddress((void**)&hd,    g_hd);
    cudaGetSymbolAddress((void**)&hp,    g_hp);
    cudaGetSymbolAddress((void**)&fs_dp, g_fs_dp);
    cudaGetSymbolAddress((void**)&fd_dp, g_fd_dp);
    cudaGetSymbolAddress((void**)&fs_pd, g_fs_pd);
    cudaGetSymbolAddress((void**)&fd_pd, g_fd_pd);
    cudaGetSymbolAddress((void**)&agg_p, g_agg_p);
    cudaGetSymbolAddress((void**)&agg_d, g_agg_d);
    cudaGetSymbolAddress((void**)&el_dp, g_el_dp);
    cudaGetSymbolAddress((void**)&er_dp, g_er_dp);
    cudaGetSymbolAddress((void**)&el_pd, g_el_pd);
    cudaGetSymbolAddress((void**)&er_pd, g_er_pd);
    cudaGetSymbolAddress((void**)&s_p,   g_s_p);
    cudaGetSymbolAddress((void**)&s_d,   g_s_d);
    cudaGetSymbolAddress((void**)&ex_dp, g_ex_dp);
    cudaGetSymbolAddress((void**)&ex_pd, g_ex_pd);

    cudaFuncSetAttribute(gemm_wmma, cudaFuncAttributeMaxDynamicSharedMemorySize, GW_SMEM);

    const int gb  = (ND + 127) / 128;   // 782 (ND == NP)
    const int hdB = (int)(((size_t)ND * 32 + 255) / 256);
    const int iaB = (int)(((size_t)ND * 128 + 255) / 256);
    const int e1B = (EE + 255) / 256;
    const int e2B = (int)(((size_t)EE * 32 + 255) / 256);

    // input projections + relu
    gemm_wmma<<<gb, 256, GW_SMEM>>>(x_drug, W_in_d, b_in_d, hd, ND, 1);
    gemm_wmma<<<gb, 256, GW_SMEM>>>(x_prot, W_in_p, b_in_p, hp, NP, 1);
    // GAT feature projections
    gemm_wmma<<<gb, 256, GW_SMEM>>>(hd, W_dp, nullptr, fs_dp, ND, 0);
    gemm_wmma<<<gb, 256, GW_SMEM>>>(hp, W_dp, nullptr, fd_dp, NP, 0);
    gemm_wmma<<<gb, 256, GW_SMEM>>>(hp, W_pd, nullptr, fs_pd, NP, 0);
    gemm_wmma<<<gb, 256, GW_SMEM>>>(hd, W_pd, nullptr, fd_pd, ND, 0);
    // attention logit halves
    headdot<<<hdB, 256>>>(fs_dp, al_dp, el_dp, ND);
    headdot<<<hdB, 256>>>(fd_dp, ar_dp, er_dp, NP);
    headdot<<<hdB, 256>>>(fs_pd, al_pd, el_pd, NP);
    headdot<<<hdB, 256>>>(fd_pd, ar_pd, er_pd, ND);
    // aggregation buffers (agg preloaded with GAT bias) + denominators
    init_agg<<<iaB, 256>>>(agg_p, bias_dp, s_p, NP);
    init_agg<<<iaB, 256>>>(agg_d, bias_pd, s_d, ND);
    // edge softmax + weighted aggregation
    edge_pass1<<<e1B, 256>>>(src_dp, dst_dp, el_dp, er_dp, ex_dp, s_p, EE);
    edge_pass1<<<e1B, 256>>>(src_pd, dst_pd, el_pd, er_pd, ex_pd, s_d, EE);
    edge_pass2<<<e2B, 256>>>(src_dp, dst_dp, ex_dp, s_p, fs_dp, agg_p, EE);
    edge_pass2<<<e2B, 256>>>(src_pd, dst_pd, ex_pd, s_d, fs_pd, agg_d, EE);
    // output projections
    gemm_wmma<<<gb, 256, GW_SMEM>>>(agg_d, W_out_d, b_out_d, out, ND, 0);
    gemm_wmma<<<gb, 256, GW_SMEM>>>(agg_p, W_out_p, b_out_p, out + (size_t)ND * 128, NP, 0);
}

// round 5
// speedup vs baseline: 1.8832x; 1.8832x over previous
#include <cuda_runtime.h>
#include <cuda_bf16.h>
#include <math.h>
#include <stdint.h>
#include <mma.h>

using namespace nvcuda;

#define ND 100000
#define NP 100000
#define EE 800000

// ---------------- scratch (__device__ globals; no allocations) ----------------
__device__ float g_hd[ND * 128];
__device__ float g_hp[NP * 128];
__device__ float g_fs_dp[ND * 128];
__device__ float g_fd_dp[NP * 128];
__device__ float g_fs_pd[NP * 128];
__device__ float g_fd_pd[ND * 128];
__device__ float g_agg_p[NP * 128];
__device__ float g_agg_d[ND * 128];
__device__ float g_el_dp[ND * 4];
__device__ float g_er_dp[NP * 4];
__device__ float g_el_pd[NP * 4];
__device__ float g_er_pd[ND * 4];
__device__ float g_s_p[NP * 4];
__device__ float g_s_d[ND * 4];
__device__ float g_ex_dp[EE * 4];
__device__ float g_ex_pd[EE * 4];

// ---------------- helpers ----------------
__device__ __forceinline__ void red_add_v4(float* addr, float4 v) {
    asm volatile("red.global.add.v4.f32 [%0], {%1,%2,%3,%4};"
                 :: "l"(addr), "f"(v.x), "f"(v.y), "f"(v.z), "f"(v.w) : "memory");
}
__device__ __forceinline__ float lrelu_exp(float v) {
    // leaky_relu(v,0.2) then exp; softmax max-shift omitted (shift-invariant, |e| = O(1))
    return expf(v > 0.f ? v : 0.2f * v);
}

// split v into bf16 hi + bf16 lo (v ~= hi + lo), store 4 consecutive
__device__ __forceinline__ void split4(float4 v, __nv_bfloat16* hi, __nv_bfloat16* lo) {
    __nv_bfloat16 h0 = __float2bfloat16(v.x);
    __nv_bfloat16 h1 = __float2bfloat16(v.y);
    __nv_bfloat16 h2 = __float2bfloat16(v.z);
    __nv_bfloat16 h3 = __float2bfloat16(v.w);
    __nv_bfloat16 l0 = __float2bfloat16(v.x - __bfloat162float(h0));
    __nv_bfloat16 l1 = __float2bfloat16(v.y - __bfloat162float(h1));
    __nv_bfloat16 l2 = __float2bfloat16(v.z - __bfloat162float(h2));
    __nv_bfloat16 l3 = __float2bfloat16(v.w - __bfloat162float(h3));
    __nv_bfloat162* H = (__nv_bfloat162*)hi;
    __nv_bfloat162* L = (__nv_bfloat162*)lo;
    H[0] = __nv_bfloat162(h0, h1); H[1] = __nv_bfloat162(h2, h3);
    L[0] = __nv_bfloat162(l0, l1); L[1] = __nv_bfloat162(l2, l3);
}

// ---------------- bf16 wmma GEMM: C[n,128] = A[n,128] @ B[128,128] (+bias,+relu) ----------------
// 3-term bf16 split: D += Ahi*Bhi + Ahi*Blo + Alo*Bhi  (~1e-5 accuracy).
// CTA tile 64x128, K=128 fully resident, 128 threads (4 warps, warp = 16 rows x 128 cols).
#define BLD 136                       // smem row stride in halves (272 B)
#define SM_BH 0
#define SM_BL (128 * BLD * 2)         // 34816
#define SM_AH (2 * 128 * BLD * 2)     // 69632
#define SM_AL (SM_AH + 64 * BLD * 2)  // 87040
#define SM_BIAS (SM_AH + 2 * 64 * BLD * 2)  // 104448 (bias tile 16x128 f32)
#define SM_EPI SM_AH                  // slow-path epilogue reuses A region (needs 32KB)
#define GW_SMEM (SM_BIAS + 16 * 128 * 4)    // 112640 bytes -> 2 CTAs/SM

__global__ void __launch_bounds__(128, 2)
gemm_bf16(const float* __restrict__ A, const float* __restrict__ B,
          const float* __restrict__ bias, float* __restrict__ C,
          int n, int relu_flag)
{
    extern __shared__ char sm[];
    __nv_bfloat16* Bh = (__nv_bfloat16*)(sm + SM_BH);
    __nv_bfloat16* Bl = (__nv_bfloat16*)(sm + SM_BL);
    __nv_bfloat16* Ah = (__nv_bfloat16*)(sm + SM_AH);
    __nv_bfloat16* Al = (__nv_bfloat16*)(sm + SM_AL);
    float* biasT = (float*)(sm + SM_BIAS);

    const int tid = threadIdx.x;
    const int warp = tid >> 5;
    const int rowbase = blockIdx.x * 64;

    // B: 128x128 f32 -> bf16 hi/lo smem (row k, col n)
    #pragma unroll
    for (int t = tid; t < 4096; t += 128) {
        int r = t >> 5, q = t & 31;
        float4 v = *(const float4*)(B + (size_t)r * 128 + q * 4);
        split4(v, Bh + r * BLD + q * 4, Bl + r * BLD + q * 4);
    }
    // A tile: 64x128 f32 -> bf16 hi/lo smem (guarded)
    #pragma unroll
    for (int t = tid; t < 2048; t += 128) {
        int r = t >> 5, q = t & 31;
        int gr = rowbase + r;
        float4 v = make_float4(0.f, 0.f, 0.f, 0.f);
        if (gr < n) v = *(const float4*)(A + (size_t)gr * 128 + q * 4);
        split4(v, Ah + r * BLD + q * 4, Al + r * BLD + q * 4);
    }
    // bias broadcast tile 16x128
    #pragma unroll
    for (int t = tid; t < 2048; t += 128) {
        int c = t & 127;
        biasT[t] = bias ? __ldg(bias + c) : 0.f;
    }
    __syncthreads();

    // accumulators: 8 n-frags, init = bias
    wmma::fragment<wmma::accumulator, 16, 16, 16, float> acc[8];
    #pragma unroll
    for (int j = 0; j < 8; j++)
        wmma::load_matrix_sync(acc[j], biasT + j * 16, 128, wmma::mem_row_major);

    #pragma unroll
    for (int ks = 0; ks < 8; ks++) {
        wmma::fragment<wmma::matrix_a, 16, 16, 16, __nv_bfloat16, wmma::row_major> ah, al;
        wmma::load_matrix_sync(ah, Ah + (warp * 16) * BLD + ks * 16, BLD);
        wmma::load_matrix_sync(al, Al + (warp * 16) * BLD + ks * 16, BLD);
        #pragma unroll
        for (int j = 0; j < 8; j++) {
            wmma::fragment<wmma::matrix_b, 16, 16, 16, __nv_bfloat16, wmma::row_major> bh, bl;
            wmma::load_matrix_sync(bh, Bh + (ks * 16) * BLD + j * 16, BLD);
            wmma::load_matrix_sync(bl, Bl + (ks * 16) * BLD + j * 16, BLD);
            wmma::mma_sync(acc[j], ah, bh, acc[j]);
            wmma::mma_sync(acc[j], ah, bl, acc[j]);
            wmma::mma_sync(acc[j], al, bh, acc[j]);
        }
    }

    if (relu_flag) {
        #pragma unroll
        for (int j = 0; j < 8; j++)
            #pragma unroll
            for (int t = 0; t < acc[j].num_elements; t++)
                acc[j].x[t] = fmaxf(acc[j].x[t], 0.f);
    }

    if (rowbase + 64 <= n) {
        // fast path: direct fragment stores
        float* crow = C + (size_t)(rowbase + warp * 16) * 128;
        #pragma unroll
        for (int j = 0; j < 8; j++)
            wmma::store_matrix_sync(crow + j * 16, acc[j], 128, wmma::mem_row_major);
    } else {
        // boundary CTA: bounce through smem, predicated copy
        __syncthreads();   // done reading A region
        float* epi = (float*)(sm + SM_EPI);   // [64][128]
        #pragma unroll
        for (int j = 0; j < 8; j++)
            wmma::store_matrix_sync(epi + (warp * 16) * 128 + j * 16, acc[j], 128,
                                    wmma::mem_row_major);
        __syncthreads();
        #pragma unroll
        for (int t = tid; t < 2048; t += 128) {
            int r = t >> 5, q = t & 31;
            int gr = rowbase + r;
            if (gr < n)
                *(float4*)(C + (size_t)gr * 128 + q * 4) = *(const float4*)(epi + r * 128 + q * 4);
        }
    }
}

// ---------------- per-head dot: out[n][h] = sum_d F[n][h*32+d] * attn[h][d] ----------------
__global__ void headdot(const float* __restrict__ F, const float* __restrict__ attn,
                        float* __restrict__ out, int n)
{
    int gw = (int)((blockIdx.x * (size_t)blockDim.x + threadIdx.x) >> 5);
    int lane = threadIdx.x & 31;
    if (gw >= n) return;
    int head = lane >> 3, part = lane & 7;
    float4 f = ((const float4*)F)[(size_t)gw * 32 + lane];
    float4 av = ((const float4*)attn)[head * 8 + part];
    float v = f.x * av.x + f.y * av.y + f.z * av.z + f.w * av.w;
    v += __shfl_down_sync(0xffffffffu, v, 4);
    v += __shfl_down_sync(0xffffffffu, v, 2);
    v += __shfl_down_sync(0xffffffffu, v, 1);
    if (part == 0) out[gw * 4 + head] = v;
}

__global__ void init_agg(float* __restrict__ agg, const float* __restrict__ bias,
                         float* __restrict__ ssum, int n)
{
    size_t i = blockIdx.x * (size_t)blockDim.x + threadIdx.x;
    if (i < (size_t)n * 128) agg[i] = bias[i & 127];
    if (i < (size_t)n * 4) ssum[i] = 0.f;
}

__global__ void edge_pass1(const int* __restrict__ src, const int* __restrict__ dst,
                           const float* __restrict__ el, const float* __restrict__ er,
                           float* __restrict__ exb, float* __restrict__ ssum, int ne)
{
    int e = blockIdx.x * blockDim.x + threadIdx.x;
    if (e >= ne) return;
    int s = src[e], d = dst[e];
    float4 a = ((const float4*)el)[s];
    float4 b = ((const float4*)er)[d];
    float4 x;
    x.x = lrelu_exp(a.x + b.x);
    x.y = lrelu_exp(a.y + b.y);
    x.z = lrelu_exp(a.z + b.z);
    x.w = lrelu_exp(a.w + b.w);
    ((float4*)exb)[e] = x;
    red_add_v4(ssum + (size_t)d * 4, x);
}

__global__ void edge_pass2(const int* __restrict__ src, const int* __restrict__ dst,
                           const float* __restrict__ exb, const float* __restrict__ ssum,
                           const float* __restrict__ fs, float* __restrict__ agg, int ne)
{
    int w = (int)((blockIdx.x * (size_t)blockDim.x + threadIdx.x) >> 5);
    int lane = threadIdx.x & 31;
    if (w >= ne) return;
    int s = src[w], d = dst[w];
    int head = lane >> 3;
    float a = exb[(size_t)w * 4 + head] / ssum[(size_t)d * 4 + head];
    float4 f = ((const float4*)fs)[(size_t)s * 32 + lane];
    float4 m = make_float4(a * f.x, a * f.y, a * f.z, a * f.w);
    red_add_v4(agg + (size_t)d * 128 + lane * 4, m);
}

// ---------------- launch ----------------
extern "C" void kernel_launch(void* const* d_in, const int* in_sizes, int n_in,
                              void* d_out, int out_size)
{
    const float* x_drug  = (const float*)d_in[0];
    const float* x_prot  = (const float*)d_in[1];
    const int*   src_dp  = (const int*)d_in[2];
    const int*   dst_dp  = (const int*)d_in[3];
    const int*   src_pd  = (const int*)d_in[4];
    const int*   dst_pd  = (const int*)d_in[5];
    const float* W_in_d  = (const float*)d_in[6];
    const float* b_in_d  = (const float*)d_in[7];
    const float* W_in_p  = (const float*)d_in[8];
    const float* b_in_p  = (const float*)d_in[9];
    const float* W_dp    = (const float*)d_in[10];
    const float* al_dp   = (const float*)d_in[11];
    const float* ar_dp   = (const float*)d_in[12];
    const float* bias_dp = (const float*)d_in[13];
    const float* W_pd    = (const float*)d_in[14];
    const float* al_pd   = (const float*)d_in[15];
    const float* ar_pd   = (const float*)d_in[16];
    const float* bias_pd = (const float*)d_in[17];
    const float* W_out_d = (const float*)d_in[18];
    const float* b_out_d = (const float*)d_in[19];
    const float* W_out_p = (const float*)d_in[20];
    const float* b_out_p = (const float*)d_in[21];
    float* out = (float*)d_out;

    float *hd, *hp, *fs_dp, *fd_dp, *fs_pd, *fd_pd, *agg_p, *agg_d;
    float *el_dp, *er_dp, *el_pd, *er_pd, *s_p, *s_d, *ex_dp, *ex_pd;
    cudaGetSymbolAddress((void**)&hd,    g_hd);
    cudaGetSymbolAddress((void**)&hp,    g_hp);
    cudaGetSymbolAddress((void**)&fs_dp, g_fs_dp);
    cudaGetSymbolAddress((void**)&fd_dp, g_fd_dp);
    cudaGetSymbolAddress((void**)&fs_pd, g_fs_pd);
    cudaGetSymbolAddress((void**)&fd_pd, g_fd_pd);
    cudaGetSymbolAddress((void**)&agg_p, g_agg_p);
    cudaGetSymbolAddress((void**)&agg_d, g_agg_d);
    cudaGetSymbolAddress((void**)&el_dp, g_el_dp);
    cudaGetSymbolAddress((void**)&er_dp, g_er_dp);
    cudaGetSymbolAddress((void**)&el_pd, g_el_pd);
    cudaGetSymbolAddress((void**)&er_pd, g_er_pd);
    cudaGetSymbolAddress((void**)&s_p,   g_s_p);
    cudaGetSymbolAddress((void**)&s_d,   g_s_d);
    cudaGetSymbolAddress((void**)&ex_dp, g_ex_dp);
    cudaGetSymbolAddress((void**)&ex_pd, g_ex_pd);

    cudaFuncSetAttribute(gemm_bf16, cudaFuncAttributeMaxDynamicSharedMemorySize, GW_SMEM);

    const int gb  = (ND + 63) / 64;     // 1563 (ND == NP)
    const int hdB = (int)(((size_t)ND * 32 + 255) / 256);
    const int iaB = (int)(((size_t)ND * 128 + 255) / 256);
    const int e1B = (EE + 255) / 256;
    const int e2B = (int)(((size_t)EE * 32 + 255) / 256);

    // input projections + relu
    gemm_bf16<<<gb, 128, GW_SMEM>>>(x_drug, W_in_d, b_in_d, hd, ND, 1);
    gemm_bf16<<<gb, 128, GW_SMEM>>>(x_prot, W_in_p, b_in_p, hp, NP, 1);
    // GAT feature projections
    gemm_bf16<<<gb, 128, GW_SMEM>>>(hd, W_dp, nullptr, fs_dp, ND, 0);
    gemm_bf16<<<gb, 128, GW_SMEM>>>(hp, W_dp, nullptr, fd_dp, NP, 0);
    gemm_bf16<<<gb, 128, GW_SMEM>>>(hp, W_pd, nullptr, fs_pd, NP, 0);
    gemm_bf16<<<gb, 128, GW_SMEM>>>(hd, W_pd, nullptr, fd_pd, ND, 0);
    // attention logit halves
    headdot<<<hdB, 256>>>(fs_dp, al_dp, el_dp, ND);
    headdot<<<hdB, 256>>>(fd_dp, ar_dp, er_dp, NP);
    headdot<<<hdB, 256>>>(fs_pd, al_pd, el_pd, NP);
    headdot<<<hdB, 256>>>(fd_pd, ar_pd, er_pd, ND);
    // aggregation buffers (agg preloaded with GAT bias) + denominators
    init_agg<<<iaB, 256>>>(agg_p, bias_dp, s_p, NP);
    init_agg<<<iaB, 256>>>(agg_d, bias_pd, s_d, ND);
    // edge softmax + weighted aggregation
    edge_pass1<<<e1B, 256>>>(src_dp, dst_dp, el_dp, er_dp, ex_dp, s_p, EE);
    edge_pass1<<<e1B, 256>>>(src_pd, dst_pd, el_pd, er_pd, ex_pd, s_d, EE);
    edge_pass2<<<e2B, 256>>>(src_dp, dst_dp, ex_dp, s_p, fs_dp, agg_p, EE);
    edge_pass2<<<e2B, 256>>>(src_pd, dst_pd, ex_pd, s_d, fs_pd, agg_d, EE);
    // output projections
    gemm_bf16<<<gb, 128, GW_SMEM>>>(agg_d, W_out_d, b_out_d, out, ND, 0);
    gemm_bf16<<<gb, 128, GW_SMEM>>>(agg_p, W_out_p, b_out_p, out + (size_t)ND * 128, NP, 0);
}

// round 9
// speedup vs baseline: 2.0387x; 1.0826x over previous
#include <cuda_runtime.h>
#include <cuda_bf16.h>
#include <math.h>
#include <stdint.h>
#include <mma.h>

using namespace nvcuda;

#define ND 100000
#define NP 100000
#define EE 800000

// ---------------- scratch (__device__ globals; no allocations) ----------------
__device__ float g_hd[ND * 128];
__device__ float g_hp[NP * 128];
__device__ float g_fs_dp[ND * 128];
__device__ float g_fd_dp[NP * 128];
__device__ float g_fs_pd[NP * 128];
__device__ float g_fd_pd[ND * 128];
__device__ float g_agg_p[NP * 128];
__device__ float g_agg_d[ND * 128];
__device__ float g_el_dp[ND * 4];
__device__ float g_er_dp[NP * 4];
__device__ float g_el_pd[NP * 4];
__device__ float g_er_pd[ND * 4];
__device__ float g_s_p[NP * 4];
__device__ float g_s_d[ND * 4];
__device__ float g_ex_dp[EE * 4];
__device__ float g_ex_pd[EE * 4];

// ---------------- helpers ----------------
__device__ __forceinline__ void red_add_v4(float* addr, float4 v) {
    asm volatile("red.global.add.v4.f32 [%0], {%1,%2,%3,%4};"
                 :: "l"(addr), "f"(v.x), "f"(v.y), "f"(v.z), "f"(v.w) : "memory");
}
__device__ __forceinline__ float lrelu_exp(float v) {
    // leaky_relu(v,0.2) then exp; softmax max-shift omitted (shift-invariant, |e| = O(1))
    return expf(v > 0.f ? v : 0.2f * v);
}

// split v into bf16 hi + bf16 lo (v ~= hi + lo), store 4 consecutive
__device__ __forceinline__ void split4(float4 v, __nv_bfloat16* hi, __nv_bfloat16* lo) {
    __nv_bfloat16 h0 = __float2bfloat16(v.x);
    __nv_bfloat16 h1 = __float2bfloat16(v.y);
    __nv_bfloat16 h2 = __float2bfloat16(v.z);
    __nv_bfloat16 h3 = __float2bfloat16(v.w);
    __nv_bfloat16 l0 = __float2bfloat16(v.x - __bfloat162float(h0));
    __nv_bfloat16 l1 = __float2bfloat16(v.y - __bfloat162float(h1));
    __nv_bfloat16 l2 = __float2bfloat16(v.z - __bfloat162float(h2));
    __nv_bfloat16 l3 = __float2bfloat16(v.w - __bfloat162float(h3));
    __nv_bfloat162* H = (__nv_bfloat162*)hi;
    __nv_bfloat162* L = (__nv_bfloat162*)lo;
    H[0] = __nv_bfloat162(h0, h1); H[1] = __nv_bfloat162(h2, h3);
    L[0] = __nv_bfloat162(l0, l1); L[1] = __nv_bfloat162(l2, l3);
}

// ---------------- bf16 wmma GEMM: C[n,128] = A[n,128] @ B[128,128] (+bias,+relu) ----------------
// 3-term bf16 split: D += Ahi*Bhi + Ahi*Blo + Alo*Bhi  (~1e-5 accuracy).
// CTA tile 256x128, K=128 fully resident, 256 threads / 8 warps, warp = 32 rows x 128 cols.
#define BLD 136                          // smem row stride in halves (272 B)
#define SM_BH 0
#define SM_BL (128 * BLD * 2)            // 34816
#define SM_AH (2 * 128 * BLD * 2)        // 69632
#define SM_AL (SM_AH + 256 * BLD * 2)    // 139264
#define SM_BIAS (SM_AH + 2 * 256 * BLD * 2)  // 208896 (bias tile 16x128 f32)
#define SM_EPI SM_AH                     // boundary epilogue reuses A region (256*128*4 = 128KB)
#define GW_SMEM (SM_BIAS + 16 * 128 * 4) // 217088 bytes

__global__ void __launch_bounds__(256, 1)
gemm_bf16(const float* __restrict__ A, const float* __restrict__ B,
          const float* __restrict__ bias, float* __restrict__ C,
          int n, int relu_flag)
{
    extern __shared__ char sm[];
    __nv_bfloat16* Bh = (__nv_bfloat16*)(sm + SM_BH);
    __nv_bfloat16* Bl = (__nv_bfloat16*)(sm + SM_BL);
    __nv_bfloat16* Ah = (__nv_bfloat16*)(sm + SM_AH);
    __nv_bfloat16* Al = (__nv_bfloat16*)(sm + SM_AL);
    float* biasT = (float*)(sm + SM_BIAS);

    const int tid = threadIdx.x;
    const int warp = tid >> 5;
    const int lane = tid & 31;
    const int rowbase = blockIdx.x * 256;

    // B: 128x128 f32 -> bf16 hi/lo smem (row k, col n)
    #pragma unroll
    for (int t = tid; t < 4096; t += 256) {
        int r = t >> 5, q = t & 31;
        float4 v = *(const float4*)(B + (size_t)r * 128 + q * 4);
        split4(v, Bh + r * BLD + q * 4, Bl + r * BLD + q * 4);
    }
    // bias broadcast tile 16x128
    #pragma unroll
    for (int t = tid; t < 2048; t += 256) {
        int c = t & 127;
        biasT[t] = bias ? __ldg(bias + c) : 0.f;
    }
    // A tile: warp-local 32 rows x 128 cols (guarded)
    {
        const int wr = warp * 32;
        #pragma unroll
        for (int t = lane; t < 1024; t += 32) {
            int r = t >> 5, q = t & 31;
            int gr = rowbase + wr + r;
            float4 v = make_float4(0.f, 0.f, 0.f, 0.f);
            if (gr < n) v = *(const float4*)(A + (size_t)gr * 128 + q * 4);
            split4(v, Ah + (wr + r) * BLD + q * 4, Al + (wr + r) * BLD + q * 4);
        }
    }
    __syncthreads();

    // accumulators: 2 row-frags x 8 col-frags, init = bias
    wmma::fragment<wmma::accumulator, 16, 16, 16, float> acc[2][8];
    #pragma unroll
    for (int i = 0; i < 2; i++)
        #pragma unroll
        for (int j = 0; j < 8; j++)
            wmma::load_matrix_sync(acc[i][j], biasT + j * 16, 128, wmma::mem_row_major);

    #pragma unroll
    for (int ks = 0; ks < 8; ks++) {
        wmma::fragment<wmma::matrix_a, 16, 16, 16, __nv_bfloat16, wmma::row_major> ah[2], al[2];
        #pragma unroll
        for (int i = 0; i < 2; i++) {
            wmma::load_matrix_sync(ah[i], Ah + (warp * 32 + i * 16) * BLD + ks * 16, BLD);
            wmma::load_matrix_sync(al[i], Al + (warp * 32 + i * 16) * BLD + ks * 16, BLD);
        }
        #pragma unroll
        for (int j = 0; j < 8; j++) {
            wmma::fragment<wmma::matrix_b, 16, 16, 16, __nv_bfloat16, wmma::row_major> bh, bl;
            wmma::load_matrix_sync(bh, Bh + (ks * 16) * BLD + j * 16, BLD);
            wmma::load_matrix_sync(bl, Bl + (ks * 16) * BLD + j * 16, BLD);
            #pragma unroll
            for (int i = 0; i < 2; i++) {
                wmma::mma_sync(acc[i][j], ah[i], bh, acc[i][j]);
                wmma::mma_sync(acc[i][j], ah[i], bl, acc[i][j]);
                wmma::mma_sync(acc[i][j], al[i], bh, acc[i][j]);
            }
        }
    }

    if (relu_flag) {
        #pragma unroll
        for (int i = 0; i < 2; i++)
            #pragma unroll
            for (int j = 0; j < 8; j++)
                #pragma unroll
                for (int t = 0; t < acc[i][j].num_elements; t++)
                    acc[i][j].x[t] = fmaxf(acc[i][j].x[t], 0.f);
    }

    if (rowbase + 256 <= n) {
        // fast path: direct fragment stores
        #pragma unroll
        for (int i = 0; i < 2; i++) {
            float* crow = C + (size_t)(rowbase + warp * 32 + i * 16) * 128;
            #pragma unroll
            for (int j = 0; j < 8; j++)
                wmma::store_matrix_sync(crow + j * 16, acc[i][j], 128, wmma::mem_row_major);
        }
    } else {
        // boundary CTA (uniform branch): bounce through smem, predicated copy
        __syncthreads();   // done reading A region
        float* epi = (float*)(sm + SM_EPI);   // [256][128]
        #pragma unroll
        for (int i = 0; i < 2; i++)
            #pragma unroll
            for (int j = 0; j < 8; j++)
                wmma::store_matrix_sync(epi + (warp * 32 + i * 16) * 128 + j * 16,
                                        acc[i][j], 128, wmma::mem_row_major);
        __syncthreads();
        #pragma unroll
        for (int t = tid; t < 8192; t += 256) {
            int r = t >> 5, q = t & 31;
            int gr = rowbase + r;
            if (gr < n)
                *(float4*)(C + (size_t)gr * 128 + q * 4) = *(const float4*)(epi + r * 128 + q * 4);
        }
    }
}

// ---------------- per-head dot: out[n][h] = sum_d F[n][h*32+d] * attn[h][d] ----------------
__global__ void headdot(const float* __restrict__ F, const float* __restrict__ attn,
                        float* __restrict__ out, int n)
{
    int gw = (int)((blockIdx.x * (size_t)blockDim.x + threadIdx.x) >> 5);
    int lane = threadIdx.x & 31;
    if (gw >= n) return;
    int head = lane >> 3, part = lane & 7;
    float4 f = ((const float4*)F)[(size_t)gw * 32 + lane];
    float4 av = ((const float4*)attn)[head * 8 + part];
    float v = f.x * av.x + f.y * av.y + f.z * av.z + f.w * av.w;
    v += __shfl_down_sync(0xffffffffu, v, 4);
    v += __shfl_down_sync(0xffffffffu, v, 2);
    v += __shfl_down_sync(0xffffffffu, v, 1);
    if (part == 0) out[gw * 4 + head] = v;
}

__global__ void init_agg(float* __restrict__ agg, const float* __restrict__ bias,
                         float* __restrict__ ssum, int n)
{
    size_t i = blockIdx.x * (size_t)blockDim.x + threadIdx.x;
    if (i < (size_t)n * 128) agg[i] = bias[i & 127];
    if (i < (size_t)n * 4) ssum[i] = 0.f;
}

__global__ void edge_pass1(const int* __restrict__ src, const int* __restrict__ dst,
                           const float* __restrict__ el, const float* __restrict__ er,
                           float* __restrict__ exb, float* __restrict__ ssum, int ne)
{
    int e = blockIdx.x * blockDim.x + threadIdx.x;
    if (e >= ne) return;
    int s = src[e], d = dst[e];
    float4 a = ((const float4*)el)[s];
    float4 b = ((const float4*)er)[d];
    float4 x;
    x.x = lrelu_exp(a.x + b.x);
    x.y = lrelu_exp(a.y + b.y);
    x.z = lrelu_exp(a.z + b.z);
    x.w = lrelu_exp(a.w + b.w);
    ((float4*)exb)[e] = x;
    red_add_v4(ssum + (size_t)d * 4, x);
}

__global__ void edge_pass2(const int* __restrict__ src, const int* __restrict__ dst,
                           const float* __restrict__ exb, const float* __restrict__ ssum,
                           const float* __restrict__ fs, float* __restrict__ agg, int ne)
{
    int w = (int)((blockIdx.x * (size_t)blockDim.x + threadIdx.x) >> 5);
    int lane = threadIdx.x & 31;
    if (w >= ne) return;
    int s = src[w], d = dst[w];
    int head = lane >> 3;
    float a = exb[(size_t)w * 4 + head] / ssum[(size_t)d * 4 + head];
    float4 f = ((const float4*)fs)[(size_t)s * 32 + lane];
    float4 m = make_float4(a * f.x, a * f.y, a * f.z, a * f.w);
    red_add_v4(agg + (size_t)d * 128 + lane * 4, m);
}

// ---------------- launch ----------------
extern "C" void kernel_launch(void* const* d_in, const int* in_sizes, int n_in,
                              void* d_out, int out_size)
{
    const float* x_drug  = (const float*)d_in[0];
    const float* x_prot  = (const float*)d_in[1];
    const int*   src_dp  = (const int*)d_in[2];
    const int*   dst_dp  = (const int*)d_in[3];
    const int*   src_pd  = (const int*)d_in[4];
    const int*   dst_pd  = (const int*)d_in[5];
    const float* W_in_d  = (const float*)d_in[6];
    const float* b_in_d  = (const float*)d_in[7];
    const float* W_in_p  = (const float*)d_in[8];
    const float* b_in_p  = (const float*)d_in[9];
    const float* W_dp    = (const float*)d_in[10];
    const float* al_dp   = (const float*)d_in[11];
    const float* ar_dp   = (const float*)d_in[12];
    const float* bias_dp = (const float*)d_in[13];
    const float* W_pd    = (const float*)d_in[14];
    const float* al_pd   = (const float*)d_in[15];
    const float* ar_pd   = (const float*)d_in[16];
    const float* bias_pd = (const float*)d_in[17];
    const float* W_out_d = (const float*)d_in[18];
    const float* b_out_d = (const float*)d_in[19];
    const float* W_out_p = (const float*)d_in[20];
    const float* b_out_p = (const float*)d_in[21];
    float* out = (float*)d_out;

    float *hd, *hp, *fs_dp, *fd_dp, *fs_pd, *fd_pd, *agg_p, *agg_d;
    float *el_dp, *er_dp, *el_pd, *er_pd, *s_p, *s_d, *ex_dp, *ex_pd;
    cudaGetSymbolAddress((void**)&hd,    g_hd);
    cudaGetSymbolAddress((void**)&hp,    g_hp);
    cudaGetSymbolAddress((void**)&fs_dp, g_fs_dp);
    cudaGetSymbolAddress((void**)&fd_dp, g_fd_dp);
    cudaGetSymbolAddress((void**)&fs_pd, g_fs_pd);
    cudaGetSymbolAddress((void**)&fd_pd, g_fd_pd);
    cudaGetSymbolAddress((void**)&agg_p, g_agg_p);
    cudaGetSymbolAddress((void**)&agg_d, g_agg_d);
    cudaGetSymbolAddress((void**)&el_dp, g_el_dp);
    cudaGetSymbolAddress((void**)&er_dp, g_er_dp);
    cudaGetSymbolAddress((void**)&el_pd, g_el_pd);
    cudaGetSymbolAddress((void**)&er_pd, g_er_pd);
    cudaGetSymbolAddress((void**)&s_p,   g_s_p);
    cudaGetSymbolAddress((void**)&s_d,   g_s_d);
    cudaGetSymbolAddress((void**)&ex_dp, g_ex_dp);
    cudaGetSymbolAddress((void**)&ex_pd, g_ex_pd);

    cudaFuncSetAttribute(gemm_bf16, cudaFuncAttributeMaxDynamicSharedMemorySize, GW_SMEM);

    const int gb  = (ND + 255) / 256;   // 391 (ND == NP)
    const int hdB = (int)(((size_t)ND * 32 + 255) / 256);
    const int iaB = (int)(((size_t)ND * 128 + 255) / 256);
    const int e1B = (EE + 255) / 256;
    const int e2B = (int)(((size_t)EE * 32 + 255) / 256);

    // input projections + relu
    gemm_bf16<<<gb, 256, GW_SMEM>>>(x_drug, W_in_d, b_in_d, hd, ND, 1);
    gemm_bf16<<<gb, 256, GW_SMEM>>>(x_prot, W_in_p, b_in_p, hp, NP, 1);
    // GAT feature projections
    gemm_bf16<<<gb, 256, GW_SMEM>>>(hd, W_dp, nullptr, fs_dp, ND, 0);
    gemm_bf16<<<gb, 256, GW_SMEM>>>(hp, W_dp, nullptr, fd_dp, NP, 0);
    gemm_bf16<<<gb, 256, GW_SMEM>>>(hp, W_pd, nullptr, fs_pd, NP, 0);
    gemm_bf16<<<gb, 256, GW_SMEM>>>(hd, W_pd, nullptr, fd_pd, ND, 0);
    // attention logit halves
    headdot<<<hdB, 256>>>(fs_dp, al_dp, el_dp, ND);
    headdot<<<hdB, 256>>>(fd_dp, ar_dp, er_dp, NP);
    headdot<<<hdB, 256>>>(fs_pd, al_pd, el_pd, NP);
    headdot<<<hdB, 256>>>(fd_pd, ar_pd, er_pd, ND);
    // aggregation buffers (agg preloaded with GAT bias) + denominators
    init_agg<<<iaB, 256>>>(agg_p, bias_dp, s_p, NP);
    init_agg<<<iaB, 256>>>(agg_d, bias_pd, s_d, ND);
    // edge softmax + weighted aggregation
    edge_pass1<<<e1B, 256>>>(src_dp, dst_dp, el_dp, er_dp, ex_dp, s_p, EE);
    edge_pass1<<<e1B, 256>>>(src_pd, dst_pd, el_pd, er_pd, ex_pd, s_d, EE);
    edge_pass2<<<e2B, 256>>>(src_dp, dst_dp, ex_dp, s_p, fs_dp, agg_p, EE);
    edge_pass2<<<e2B, 256>>>(src_pd, dst_pd, ex_pd, s_d, fs_pd, agg_d, EE);
    // output projections
    gemm_bf16<<<gb, 256, GW_SMEM>>>(agg_d, W_out_d, b_out_d, out, ND, 0);
    gemm_bf16<<<gb, 256, GW_SMEM>>>(agg_p, W_out_p, b_out_p, out + (size_t)ND * 128, NP, 0);
}